// round 10
// baseline (speedup 1.0000x reference)
#include <cuda_runtime.h>
#include <cuda_fp16.h>
#include <cstdint>
#include <math.h>

#define BB 32
#define SS 64
#define CC 256
#define N2 4096

#define SF 96                      // stage row stride (bytes) per channel
#define STAGE_BYTES (16 * SF)      // 1536
#define WARP_BUF (4 * STAGE_BYTES) // 6144 (4 stages)
#define DSM_BYTES (8 * WARP_BUF)   // 49152

__device__ int      g_topk[SS];
__device__ int      g_vstart[BB + 1];
__device__ float    g_negsum[SS];
__device__ float    g_all[SS * SS];
__device__ uint4    g_Afr[16 * 4 * 32];   // A in MMA-fragment order [ks][mt][lane]
__device__ unsigned g_done;

__device__ __forceinline__ uint32_t smem_u32(const void* p) {
    uint32_t a;
    asm("{ .reg .u64 t; cvta.to.shared.u64 t, %1; cvt.u32.u64 %0, t; }" : "=r"(a) : "l"(p));
    return a;
}
#define CP16(dst, src) \
    asm volatile("cp.async.cg.shared.global [%0], [%1], 16;" :: "r"(dst), "l"(src))
#define CP_COMMIT() asm volatile("cp.async.commit_group;")
#define CP_WAIT2()  asm volatile("cp.async.wait_group 2;")

#define MMAF16(d, a0, a1, a2, a3, b0, b1) \
    asm volatile("mma.sync.aligned.m16n8k16.row.col.f32.f16.f16.f32 " \
                 "{%0,%1,%2,%3}, {%4,%5,%6,%7}, {%8,%9}, {%0,%1,%2,%3};" \
                 : "+f"((d)[0]), "+f"((d)[1]), "+f"((d)[2]), "+f"((d)[3]) \
                 : "r"(a0), "r"(a1), "r"(a2), "r"(a3), "r"(b0), "r"(b1))

// ---------------------------------------------------------------------------
// k_prep: bid<64 = sentence s: normalize -> fragment-order A; iou argmax.
//         bid==64: vstart prefix + negsum + g_done init.
__global__ void k_prep(const float* __restrict__ sents, const float* __restrict__ iou,
                       const int* __restrict__ ntgt) {
    int bid = blockIdx.x, tid = threadIdx.x;
    if (bid == 64) {
        if (tid < SS) g_negsum[tid] = 0.f;
        if (tid == 0) {
            g_done = 0u;
            int acc = 0;
            g_vstart[0] = 0;
            for (int b = 0; b < BB; b++) {
                acc += ntgt[b];
                if (acc > SS) acc = SS;
                g_vstart[b + 1] = acc;
            }
        }
        return;
    }
    int s = bid;
    int lane = tid & 31, w = tid >> 5;
    __shared__ float wsum[8];
    __shared__ float amax[8];
    __shared__ int   aidx[8];

    float x = sents[s * CC + tid];
    float q = x * x;
#pragma unroll
    for (int o = 16; o; o >>= 1) q += __shfl_xor_sync(~0u, q, o);
    if (lane == 0) wsum[w] = q;
    __syncthreads();
    float tot = wsum[0] + wsum[1] + wsum[2] + wsum[3] +
                wsum[4] + wsum[5] + wsum[6] + wsum[7];
    float inv = 1.f / fmaxf(sqrtf(tot), 1e-12f);
    __half h = __float2half_rn(x * inv);
    int c = tid;
    int u4 = ((c >> 4) * 4 + (s >> 4)) * 32 + (s & 7) * 4 + ((c & 7) >> 1);
    int byte = u4 * 16 + ((s >> 3) & 1) * 4 + ((c >> 3) & 1) * 8 + (c & 1) * 2;
    *(__half*)((char*)g_Afr + byte) = h;

    float best = -1.f;
    int bi = 0;
    const float* irow = iou + (size_t)s * N2;
#pragma unroll
    for (int k = 0; k < 16; k++) {
        int ij = tid + 256 * k;
        if ((ij & 63) >= (ij >> 6)) {
            float v = irow[ij];
            if (v > best) { best = v; bi = ij; }
        }
    }
#pragma unroll
    for (int o = 16; o; o >>= 1) {
        float ov = __shfl_xor_sync(~0u, best, o);
        int   oi = __shfl_xor_sync(~0u, bi, o);
        if (ov > best || (ov == best && oi < bi)) { best = ov; bi = oi; }
    }
    if (lane == 0) { amax[w] = best; aidx[w] = bi; }
    __syncthreads();
    if (tid == 0) {
        float bb = amax[0]; int ii = aidx[0];
        for (int k = 1; k < 8; k++)
            if (amax[k] > bb || (amax[k] == bb && aidx[k] < ii)) { bb = amax[k]; ii = aidx[k]; }
        g_topk[s] = ii;
    }
}

// ---------------------------------------------------------------------------
// k_main: warp-autonomous, warp-private cp.async ring (no CTA barriers in loop).
__global__ void __launch_bounds__(256, 3) k_main(const float* __restrict__ video,
                                                 const float* __restrict__ iou,
                                                 float* __restrict__ out) {
    extern __shared__ __align__(16) char dsm[];
    __shared__ float sneg[SS];
    __shared__ float red[128];
    __shared__ int   flag;

    int tid = threadIdx.x;
    int lane = tid & 31, w = tid >> 5;
    int b = blockIdx.y;
    int sid = blockIdx.x * 8 + w;          // 0..159

    // strip -> (row i, 16-col block kq)
    int i, kq;
    if (sid < 64)       { i = sid >> 2;               kq = sid & 3; }
    else if (sid < 112) { int r = sid - 64;  i = 16 + r / 3;  kq = r % 3 + 1; }
    else if (sid < 144) { int r = sid - 112; i = 32 + (r >> 1); kq = (r & 1) + 2; }
    else                { i = 48 + (sid - 144);        kq = 3; }
    int j0 = kq * 16;
    int p0 = i * 64 + j0;

    char* wbuf = dsm + w * WARP_BUF;
    uint32_t wb = smem_u32(wbuf);
    int q = lane & 3, nl = lane >> 2;

    // cp.async mapping: lane -> (channel cA & cA+8, prop group gA)
    int cA = lane >> 2, gA = lane & 3;
    const float* gsrc = video + (size_t)b * CC * N2 + p0 + gA * 4;
    uint32_t dA = cA * SF + gA * 16;
    uint32_t dB = (cA + 8) * SF + gA * 16;

    // prologue: stages 0,1,2
#pragma unroll
    for (int ks = 0; ks < 3; ks++) {
        uint32_t d = wb + ks * STAGE_BYTES;
        const float* s0 = gsrc + (size_t)(ks * 16 + cA) * N2;
        CP16(d + dA, s0);
        CP16(d + dB, s0 + (size_t)8 * N2);
        CP_COMMIT();
    }

    if (tid < SS) sneg[tid] = 0.f;
    __syncthreads();

    const uint4* Af = g_Afr + lane;
    float acc[32];
#pragma unroll
    for (int k = 0; k < 32; k++) acc[k] = 0.f;
    float ss0 = 0.f, ss1 = 0.f;

#pragma unroll
    for (int ks = 0; ks < 16; ks++) {
        CP_WAIT2();
        __syncwarp();
        const char* base = wbuf + (ks & 3) * STAGE_BYTES;
        const float* r0 = (const float*)(base + 2 * q * SF + nl * 4);
        float x0 = r0[0];
        float x1 = *(const float*)((const char*)r0 + SF);
        float x2 = *(const float*)((const char*)r0 + 8 * SF);
        float x3 = *(const float*)((const char*)r0 + 9 * SF);
        float y0 = r0[8];
        float y1 = *(const float*)((const char*)r0 + SF + 32);
        float y2 = *(const float*)((const char*)r0 + 8 * SF + 32);
        float y3 = *(const float*)((const char*)r0 + 9 * SF + 32);
        ss0 += x0 * x0 + x1 * x1 + x2 * x2 + x3 * x3;
        ss1 += y0 * y0 + y1 * y1 + y2 * y2 + y3 * y3;
        __half2 p00 = __floats2half2_rn(x0, x1);
        __half2 p01 = __floats2half2_rn(x2, x3);
        __half2 p10 = __floats2half2_rn(y0, y1);
        __half2 p11 = __floats2half2_rn(y2, y3);
        uint32_t b00 = *(uint32_t*)&p00, b01 = *(uint32_t*)&p01;
        uint32_t b10 = *(uint32_t*)&p10, b11 = *(uint32_t*)&p11;
#pragma unroll
        for (int mt = 0; mt < 4; mt++) {
            uint4 a = Af[(ks * 4 + mt) * 32];
            MMAF16(acc + mt * 8,     a.x, a.y, a.z, a.w, b00, b01);
            MMAF16(acc + mt * 8 + 4, a.x, a.y, a.z, a.w, b10, b11);
        }
        // issue stage ks+3 (buffer reuse ordered by this iter's __syncwarp)
        if (ks + 3 < 16) {
            uint32_t d = wb + ((ks + 3) & 3) * STAGE_BYTES;
            const float* s0 = gsrc + (size_t)((ks + 3) * 16 + cA) * N2;
            CP16(d + dA, s0);
            CP16(d + dB, s0 + (size_t)8 * N2);
        }
        CP_COMMIT();
    }

    // per-prop inverse norms
    ss0 += __shfl_xor_sync(~0u, ss0, 1); ss0 += __shfl_xor_sync(~0u, ss0, 2);
    ss1 += __shfl_xor_sync(~0u, ss1, 1); ss1 += __shfl_xor_sync(~0u, ss1, 2);
    float inv0 = rsqrtf(fmaxf(ss0, 1e-24f));
    float inv1 = rsqrtf(fmaxf(ss1, 1e-24f));
    float invc[4];
    invc[0] = __shfl_sync(~0u, inv0, 8 * q);
    invc[1] = __shfl_sync(~0u, inv0, 8 * q + 4);
    invc[2] = __shfl_sync(~0u, inv1, 8 * q);
    invc[3] = __shfl_sync(~0u, inv1, 8 * q + 4);

    int jc[4];
    jc[0] = j0 + 2 * q;     jc[1] = jc[0] + 1;
    jc[2] = j0 + 8 + 2 * q; jc[3] = jc[2] + 1;
    bool vj[4];
#pragma unroll
    for (int e = 0; e < 4; e++) vj[e] = (jc[e] >= i);

    int vs0 = g_vstart[b], vs1 = g_vstart[b + 1];
    int nc = 0, capC[4], capS4[4];
    for (int cs = vs0; cs < vs1; cs++) {
        int rel = g_topk[cs] - i * 64 - j0;
        if (rel >= 0 && rel < 16 && nc < 4) { capC[nc] = j0 + rel; capS4[nc] = cs; nc++; }
    }

    float rsum[8];
#pragma unroll
    for (int mt = 0; mt < 4; mt++) {
        int sA = mt * 16 + nl, sB = sA + 8;
        bool hA = (sA >= vs0 && sA < vs1);
        bool hB = (sB >= vs0 && sB < vs1);
        float rA = 0.f, rB = 0.f;
#pragma unroll
        for (int e = 0; e < 4; e++) {
            int blk = e >> 1, par = e & 1;
            float scA = acc[mt * 8 + blk * 4 + par] * invc[e];
            float scB = acc[mt * 8 + blk * 4 + 2 + par] * invc[e];
            if (vj[e]) {
                int ij = i * 64 + jc[e];
                bool posA = hA && (iou[(size_t)sA * N2 + ij] > 0.5f);
                bool posB = hB && (iou[(size_t)sB * N2 + ij] > 0.5f);
                if (!posA) rA += __expf(scA * 10.f);
                if (!posB) rB += __expf(scB * 10.f);
                for (int cc = 0; cc < nc; cc++)
                    if (capC[cc] == jc[e]) {
                        g_all[capS4[cc] * SS + sA] = scA;
                        g_all[capS4[cc] * SS + sB] = scB;
                    }
            }
        }
        rsum[mt * 2] = rA;
        rsum[mt * 2 + 1] = rB;
    }
#pragma unroll
    for (int k = 0; k < 8; k++) {
        rsum[k] += __shfl_xor_sync(~0u, rsum[k], 1);
        rsum[k] += __shfl_xor_sync(~0u, rsum[k], 2);
    }
    if (q == 0) {
#pragma unroll
        for (int mt = 0; mt < 4; mt++) {
            atomicAdd(&sneg[mt * 16 + nl], rsum[mt * 2]);
            atomicAdd(&sneg[mt * 16 + nl + 8], rsum[mt * 2 + 1]);
        }
    }
    __syncthreads();
    if (tid < SS) atomicAdd(&g_negsum[tid], sneg[tid]);

    // last-CTA final reduction
    __threadfence();
    __syncthreads();
    if (tid == 0) flag = (atomicAdd(&g_done, 1u) == (unsigned)(20 * BB - 1));
    __syncthreads();
    if (flag) {
        if (tid < SS) {
            int s = tid;
            float pos = __ldcg(&g_all[s * SS + s]);
            float sum = 0.f;
            for (int u = 0; u < SS; u++)
                if (u != s) sum += expf(__ldcg(&g_all[s * SS + u]) * 10.f);
            float pv = pos * 10.f;
            red[s] = -(pv - logf(expf(pv) + sum));
            red[64 + s] = -(pv - logf(expf(pv) + __ldcg(&g_negsum[s])));
        }
        __syncthreads();
        if (tid == 0) {
            float a = 0.f, bq = 0.f;
            for (int u = 0; u < SS; u++) { a += red[u]; bq += red[64 + u]; }
            out[0] = a / SS;
            out[1] = bq / SS;
        }
    }
}

// ---------------------------------------------------------------------------
extern "C" void kernel_launch(void* const* d_in, const int* in_sizes, int n_in,
                              void* d_out, int out_size) {
    const float* video = (const float*)d_in[0];
    const float* sents = (const float*)d_in[1];
    const int*   ntgt  = (const int*)d_in[2];
    const float* iou   = (const float*)d_in[3];
    float* out = (float*)d_out;

    cudaFuncSetAttribute(k_main, cudaFuncAttributeMaxDynamicSharedMemorySize, DSM_BYTES);
    cudaFuncSetAttribute(k_main, cudaFuncAttributePreferredSharedMemoryCarveout, 100);

    k_prep<<<65, 256>>>(sents, iou, ntgt);
    k_main<<<dim3(20, BB), 256, DSM_BYTES>>>(video, iou, out);
}